// round 2
// baseline (speedup 1.0000x reference)
#include <cuda_runtime.h>
#include <cuda_bf16.h>

#define BB 64
#define TT 8192
#define DD 64
#define NN 64

// ---------------- scratch (static device globals; no allocation) ----------------
__device__ __align__(16) float g_Acol[NN * NN];    // Acol[n*64+m] = A[m][n] (column n contiguous over m)
__device__ float g_epi[NN];                        // exp(log_pi)
__device__ __align__(16) float g_Wt[DD * NN];      // Wt[d*64+n] = mu*inv_var
__device__ __align__(16) float g_Vt[DD * NN];      // Vt[d*64+n] = -0.5*inv_var
__device__ float g_c2[NN];                         // per-state constant
__device__ __align__(16) unsigned short g_bexp[(size_t)BB * TT * NN + 1024]; // bf16 exp(logB-mb), +pad for prefetch overshoot
__device__ float g_mb[BB * TT];                    // per (b,t) max_n logB
__device__ float g_res[BB];                        // per-batch log prob

typedef unsigned long long u64;

__device__ __forceinline__ u64 fma2(u64 a, u64 b, u64 c) {
    u64 d; asm("fma.rn.f32x2 %0,%1,%2,%3;" : "=l"(d) : "l"(a), "l"(b), "l"(c)); return d;
}
__device__ __forceinline__ u64 add2(u64 a, u64 b) {
    u64 d; asm("add.rn.f32x2 %0,%1,%2;" : "=l"(d) : "l"(a), "l"(b)); return d;
}
__device__ __forceinline__ u64 pack2(float x, float y) {
    u64 d; asm("mov.b64 %0,{%1,%2};" : "=l"(d) : "f"(x), "f"(y)); return d;
}
__device__ __forceinline__ float2 unpack2(u64 a) {
    float2 f; asm("mov.b64 {%0,%1},%2;" : "=f"(f.x), "=f"(f.y) : "l"(a)); return f;
}
__device__ __forceinline__ unsigned int cvt_bf16x2(float lo, float hi) {
    unsigned int r; asm("cvt.rn.bf16x2.f32 %0, %1, %2;" : "=r"(r) : "f"(hi), "f"(lo)); return r;
}
__device__ __forceinline__ float bf16_to_f32(unsigned short u) {
    return __uint_as_float(((unsigned int)u) << 16);
}

// ---------------- kernel 1: parameter prep (1 CTA, 64 threads) ----------------
__global__ void prep_kernel(const float* __restrict__ tr, const float* __restrict__ pri,
                            const float* __restrict__ means, const float* __restrict__ lvars) {
    int n = threadIdx.x;  // 0..63
    // row-softmax of transition row n -> write A column-major for the scan kernel
    float row[NN];
    float mx = -1e30f;
    for (int j = 0; j < NN; ++j) { row[j] = tr[n * NN + j]; mx = fmaxf(mx, row[j]); }
    float s = 0.f;
    for (int j = 0; j < NN; ++j) { row[j] = expf(row[j] - mx); s += row[j]; }
    float inv = 1.0f / s;
    for (int j = 0; j < NN; ++j) g_Acol[j * NN + n] = row[j] * inv;  // Acol[col=j][row=n] = A[n][j]

    // priors
    float pm = -1e30f;
    for (int j = 0; j < NN; ++j) pm = fmaxf(pm, pri[j]);
    float ps = 0.f;
    for (int j = 0; j < NN; ++j) ps += expf(pri[j] - pm);
    g_epi[n] = expf(pri[n] - pm) / ps;  // exp(log_softmax(pri))[n]

    // emission params:  logB = c2[n] + sum_d (x_d*W[n,d] + x_d^2*V[n,d])
    float slv = 0.f, mm = 0.f;
    for (int d = 0; d < DD; ++d) {
        float lv = lvars[n * DD + d];
        float iv = expf(-lv);
        float mu = means[n * DD + d];
        g_Wt[d * NN + n] = mu * iv;
        g_Vt[d * NN + n] = -0.5f * iv;
        slv += lv;
        mm += mu * mu * iv;
    }
    g_c2[n] = -0.5f * ((float)DD * 1.8378770664093453f + slv + mm);
}

// ---------------- kernel 2: emission -> bexp (bf16) + mb (fp32) ----------------
// One thread per timestep; thread owns all 64 states (max & exp are thread-local).
__global__ __launch_bounds__(128, 2) void emis_kernel(const float* __restrict__ X) {
    __shared__ __align__(16) float Ws[DD * NN];
    __shared__ __align__(16) float Vs[DD * NN];
    __shared__ float c2s[NN];
    int tid = threadIdx.x;
    for (int i = tid; i < DD * NN; i += 128) { Ws[i] = g_Wt[i]; Vs[i] = g_Vt[i]; }
    if (tid < NN) c2s[tid] = g_c2[tid];
    __syncthreads();

    int b = blockIdx.y;
    int t = blockIdx.x * 128 + tid;
    const float4* xp = (const float4*)(X + ((size_t)b * TT + t) * DD);
    float4 xv[16];
#pragma unroll
    for (int i = 0; i < 16; ++i) xv[i] = xp[i];

    u64 acc[32];
#pragma unroll
    for (int j = 0; j < 32; ++j) acc[j] = pack2(c2s[2 * j], c2s[2 * j + 1]);

    for (int db = 0; db < 16; ++db) {
        float4 xq = xv[db];
#pragma unroll
        for (int dd = 0; dd < 4; ++dd) {
            float xd = (dd == 0) ? xq.x : (dd == 1) ? xq.y : (dd == 2) ? xq.z : xq.w;
            float xx = xd * xd;
            u64 x2 = pack2(xd, xd), q2 = pack2(xx, xx);
            const u64* W2 = (const u64*)(Ws + (db * 4 + dd) * NN);
            const u64* V2 = (const u64*)(Vs + (db * 4 + dd) * NN);
#pragma unroll
            for (int j = 0; j < 32; ++j) {
                acc[j] = fma2(x2, W2[j], acc[j]);
                acc[j] = fma2(q2, V2[j], acc[j]);
            }
        }
    }

    // per-timestep max over states, then exp and bf16 pack
    float mx = -1e30f;
#pragma unroll
    for (int j = 0; j < 32; ++j) {
        float2 f = unpack2(acc[j]);
        mx = fmaxf(mx, fmaxf(f.x, f.y));
    }
    unsigned int ob[32];
#pragma unroll
    for (int j = 0; j < 32; ++j) {
        float2 f = unpack2(acc[j]);
        float e0 = __expf(f.x - mx);
        float e1 = __expf(f.y - mx);
        ob[j] = cvt_bf16x2(e0, e1);
    }
    uint4* o4 = (uint4*)(g_bexp + ((size_t)b * TT + t) * NN);
#pragma unroll
    for (int q = 0; q < 8; ++q) o4[q] = make_uint4(ob[4 * q], ob[4 * q + 1], ob[4 * q + 2], ob[4 * q + 3]);
    g_mb[b * TT + t] = mx;
}

// ---------------- kernel 3: serial forward scan (64 CTAs, one per batch) ----------------
__device__ __forceinline__ void hmm_step(float (*shu)[NN], int& p, const u64* Ac,
                                         unsigned short bu, double& Lr, int tid, int lane) {
    const float* uin = shu[p];
    // max of input vector (runs concurrently with the matvec; any positive rescale is exact)
    float m0 = fmaxf(uin[lane], uin[lane + 32]);
#pragma unroll
    for (int o = 16; o > 0; o >>= 1) m0 = fmaxf(m0, __shfl_xor_sync(0xffffffffu, m0, o));

    const float4* up = (const float4*)uin;
    u64 a0 = 0ull, a1 = 0ull, a2 = 0ull, a3 = 0ull;  // {0.f,0.f} bit pattern
#pragma unroll
    for (int j = 0; j < 8; ++j) {
        float4 ua = up[2 * j];
        float4 ub = up[2 * j + 1];
        a0 = fma2(pack2(ua.x, ua.y), Ac[4 * j + 0], a0);
        a1 = fma2(pack2(ua.z, ua.w), Ac[4 * j + 1], a1);
        a2 = fma2(pack2(ub.x, ub.y), Ac[4 * j + 2], a2);
        a3 = fma2(pack2(ub.z, ub.w), Ac[4 * j + 3], a3);
    }
    a0 = add2(a0, a2); a1 = add2(a1, a3); a0 = add2(a0, a1);
    float2 f = unpack2(a0);
    float s = f.x + f.y;

    float w = s * bf16_to_f32(bu);
    float invr = __frcp_rn(m0);
    shu[p ^ 1][tid] = w * invr;
    if (tid == 0) Lr += (double)__logf(m0);
    __syncthreads();
    p ^= 1;
}

__global__ __launch_bounds__(64, 1) void scan_kernel() {
    __shared__ __align__(16) float shu[2][NN];
    __shared__ double shmb[NN];
    int b = blockIdx.x, tid = threadIdx.x, lane = tid & 31;

    // A column for this thread's state, packed as f32x2 pairs over m
    u64 Ac[32];
    const u64* ap = (const u64*)(g_Acol + tid * NN);
#pragma unroll
    for (int j = 0; j < 32; ++j) Ac[j] = ap[j];

    // sum of mb over t (off critical path)
    double mbs = 0.0;
    const float* mbp = g_mb + b * TT;
    for (int t2 = tid; t2 < TT; t2 += 64) mbs += (double)mbp[t2];
    shmb[tid] = mbs;

    const unsigned short* bx = g_bexp + (size_t)b * TT * NN;
    shu[0][tid] = g_epi[tid] * bf16_to_f32(bx[tid]);  // u0 = exp(log_pi)*bexp_0 ; scale mb_0 in mbs
    double Lr = 0.0;

    unsigned short cur[8], nxt[8];
#pragma unroll
    for (int k = 0; k < 8; ++k) cur[k] = bx[(size_t)(1 + k) * NN + tid];
    __syncthreads();

    int p = 0;
    int t2 = 1;
    for (; t2 + 8 <= TT; t2 += 8) {
#pragma unroll
        for (int k = 0; k < 8; ++k) nxt[k] = bx[(size_t)(t2 + 8 + k) * NN + tid];  // prefetch (pad covers overshoot)
#pragma unroll
        for (int k = 0; k < 8; ++k) hmm_step(shu, p, Ac, cur[k], Lr, tid, lane);
#pragma unroll
        for (int k = 0; k < 8; ++k) cur[k] = nxt[k];
    }
    for (; t2 < TT; ++t2) hmm_step(shu, p, Ac, bx[(size_t)t2 * NN + tid], Lr, tid, lane);

    if (tid == 0) {
        float S = 0.f;
        for (int m = 0; m < NN; ++m) S += shu[p][m];
        double mt = 0.0;
        for (int m = 0; m < NN; ++m) mt += shmb[m];
        g_res[b] = (float)(mt + Lr + (double)__logf(S));
    }
}

// ---------------- kernel 4: final reduction over batches ----------------
__global__ void final_kernel(float* __restrict__ out) {
    double s = 0.0;
    for (int b = 0; b < BB; ++b) s += (double)g_res[b];
    out[0] = (float)s;
}

// ---------------- launcher ----------------
extern "C" void kernel_launch(void* const* d_in, const int* in_sizes, int n_in,
                              void* d_out, int out_size) {
    const float* X    = (const float*)d_in[0];  // [B,T,D]
    const float* tr   = (const float*)d_in[1];  // [N,N]
    const float* pri  = (const float*)d_in[2];  // [N]
    const float* mns  = (const float*)d_in[3];  // [N,D]
    const float* lvs  = (const float*)d_in[4];  // [N,D]
    (void)in_sizes; (void)n_in; (void)out_size;

    prep_kernel<<<1, 64>>>(tr, pri, mns, lvs);
    emis_kernel<<<dim3(TT / 128, BB), 128>>>(X);
    scan_kernel<<<BB, 64>>>();
    final_kernel<<<1, 1>>>((float*)d_out);
}